// round 5
// baseline (speedup 1.0000x reference)
#include <cuda_runtime.h>
#include <cuda_fp16.h>
#include <cstdint>

#define NU 100000
#define NM 50000
#define EDGES 1000000
#define HID 128
#define DIM 64

// Precomputed per-node projections (fp16). __device__ globals = allowed scratch.
__device__ __half g_U[(size_t)NU * HID];
__device__ __half g_I[(size_t)NM * HID];
__device__ int g_idx32;   // 1 if index arrays are int32, 0 if int64

// ---------------------------------------------------------------------------
// Detect index dtype: if data is int32, reading as int64 gives nonzero high
// words (hi word = next int32 index, ~always nonzero over 256 samples).
// Scans both src and dst for robustness.
// ---------------------------------------------------------------------------
__global__ void detect_idx_kernel(const long long* __restrict__ src,
                                  const long long* __restrict__ dst) {
    long long v = src[threadIdx.x];
    long long w = dst[threadIdx.x];
    int any = (((unsigned long long)v >> 32) != 0ull) |
              (((unsigned long long)w >> 32) != 0ull);
    any = __syncthreads_or(any);
    if (threadIdx.x == 0) g_idx32 = any;
}

// ---------------------------------------------------------------------------
// Precompute: C[r][j] = sum_k A[r][k] * W1[j][kOff + k]  (+ b1[j] if given)
// A: [R,64] fp32, W1: [128,128] row-major, C: [R,128] fp16.
// Block = 256 threads, 32 rows x 128 cols per block. Thread: 4 rows x 4 cols.
// ---------------------------------------------------------------------------
__global__ __launch_bounds__(256) void precompute_kernel(
    const float* __restrict__ A, int R,
    const float* __restrict__ W1, int kOff,
    const float* __restrict__ b1,     // may be null
    __half* __restrict__ C)
{
    __shared__ float Wt[DIM][HID];    // Wt[k][j] = W1[j][kOff+k]   (32 KB)
    __shared__ float As[32][DIM];     // A tile                      (8 KB)

    const int tid = threadIdx.x;
    const int r0  = blockIdx.x * 32;

    #pragma unroll
    for (int idx = tid; idx < DIM * HID; idx += 256) {
        int k = idx >> 7, j = idx & 127;
        Wt[k][j] = W1[j * 128 + kOff + k];
    }
    for (int idx = tid; idx < 32 * DIM; idx += 256) {
        int r = idx >> 6, c = idx & 63;
        int gr = r0 + r;
        As[r][c] = (gr < R) ? A[(size_t)gr * DIM + c] : 0.f;
    }
    __syncthreads();

    const int tx = tid & 31;   // output column group: cols tx*4 .. tx*4+3
    const int ty = tid >> 5;   // rows ty, ty+8, ty+16, ty+24

    float acc[4][4];
    #pragma unroll
    for (int r = 0; r < 4; r++)
        #pragma unroll
        for (int c = 0; c < 4; c++) acc[r][c] = 0.f;

    #pragma unroll 8
    for (int k = 0; k < DIM; k++) {
        float4 w = *(const float4*)&Wt[k][tx * 4];
        #pragma unroll
        for (int r = 0; r < 4; r++) {
            float a = As[ty + r * 8][k];   // warp-broadcast LDS
            acc[r][0] = fmaf(a, w.x, acc[r][0]);
            acc[r][1] = fmaf(a, w.y, acc[r][1]);
            acc[r][2] = fmaf(a, w.z, acc[r][2]);
            acc[r][3] = fmaf(a, w.w, acc[r][3]);
        }
    }

    float4 bb = make_float4(0.f, 0.f, 0.f, 0.f);
    if (b1) bb = *(const float4*)&b1[tx * 4];

    #pragma unroll
    for (int r = 0; r < 4; r++) {
        int gr = r0 + ty + r * 8;
        if (gr < R) {
            __half2 h0 = __floats2half2_rn(acc[r][0] + bb.x, acc[r][1] + bb.y);
            __half2 h1 = __floats2half2_rn(acc[r][2] + bb.z, acc[r][3] + bb.w);
            __half2* cp = (__half2*)(C + (size_t)gr * HID + tx * 4);
            cp[0] = h0;
            cp[1] = h1;
        }
    }
}

// ---------------------------------------------------------------------------
// Edge pass: out[e][c] = sum_j relu(U[src[e]][j] + I[dst[e]][j]) * W2[c][j] + b2[c]
// 2 edges per warp (16 lanes each), 8 j's per lane, W2 slice in registers,
// 4-level xor-shuffle reduction within each 16-lane group.
// ---------------------------------------------------------------------------
__device__ __forceinline__ void edge_body(
    long long e, long long s, long long d, int g,
    const __half* __restrict__ U, const __half* __restrict__ I,
    const float* __restrict__ w2r, float b2sel, float* __restrict__ out)
{
    uint4 uv = *(const uint4*)(U + (size_t)s * HID + g * 8);
    uint4 iv = *(const uint4*)(I + (size_t)d * HID + g * 8);

    float h[8];
    {
        const __half2* u2 = (const __half2*)&uv;
        const __half2* i2 = (const __half2*)&iv;
        #pragma unroll
        for (int t = 0; t < 4; t++) {
            float2 uf = __half22float2(u2[t]);
            float2 vf = __half22float2(i2[t]);
            h[2 * t]     = fmaxf(uf.x + vf.x, 0.f);
            h[2 * t + 1] = fmaxf(uf.y + vf.y, 0.f);
        }
    }

    float acc[5];
    #pragma unroll
    for (int c = 0; c < 5; c++) {
        float a = 0.f;
        #pragma unroll
        for (int k = 0; k < 8; k++)
            a = fmaf(h[k], w2r[c * 8 + k], a);
        acc[c] = a;
    }

    // reduce across the 16 lanes of this edge-group
    #pragma unroll
    for (int off = 8; off >= 1; off >>= 1) {
        #pragma unroll
        for (int c = 0; c < 5; c++)
            acc[c] += __shfl_xor_sync(0xffffffffu, acc[c], off);
    }

    if (g < 5) {
        float v = acc[0];
        if (g == 1) v = acc[1];
        else if (g == 2) v = acc[2];
        else if (g == 3) v = acc[3];
        else if (g == 4) v = acc[4];
        out[e * 5 + g] = v + b2sel;
    }
}

__global__ __launch_bounds__(256) void edge_kernel(
    const void* __restrict__ src_raw, const void* __restrict__ dst_raw,
    const __half* __restrict__ U, const __half* __restrict__ I,
    const float* __restrict__ W2, const float* __restrict__ b2,
    float* __restrict__ out)
{
    const int lane = threadIdx.x & 31;
    const int g    = lane & 15;      // j-group within my edge (j = g*8 .. g*8+7)
    const int sub  = lane >> 4;      // which edge of the warp's pair
    const int warpId = (blockIdx.x * blockDim.x + threadIdx.x) >> 5;
    const int nWarps = (gridDim.x * blockDim.x) >> 5;

    // Preload my W2 slice: W2[c][g*8 .. g*8+7], c = 0..4  (40 regs)
    float w2r[40];
    #pragma unroll
    for (int c = 0; c < 5; c++) {
        float4 a = *(const float4*)(W2 + c * HID + g * 8);
        float4 b = *(const float4*)(W2 + c * HID + g * 8 + 4);
        w2r[c * 8 + 0] = a.x; w2r[c * 8 + 1] = a.y;
        w2r[c * 8 + 2] = a.z; w2r[c * 8 + 3] = a.w;
        w2r[c * 8 + 4] = b.x; w2r[c * 8 + 5] = b.y;
        w2r[c * 8 + 6] = b.z; w2r[c * 8 + 7] = b.w;
    }
    const float b2sel = b2[g < 5 ? g : 0];

    const int nPairs = EDGES / 2;
    if (g_idx32) {
        const int* src32 = (const int*)src_raw;
        const int* dst32 = (const int*)dst_raw;
        for (int p = warpId; p < nPairs; p += nWarps) {
            const long long e = (long long)p * 2 + sub;
            edge_body(e, src32[e], dst32[e], g, U, I, w2r, b2sel, out);
        }
    } else {
        const long long* src64 = (const long long*)src_raw;
        const long long* dst64 = (const long long*)dst_raw;
        for (int p = warpId; p < nPairs; p += nWarps) {
            const long long e = (long long)p * 2 + sub;
            edge_body(e, src64[e], dst64[e], g, U, I, w2r, b2sel, out);
        }
    }
}

// ---------------------------------------------------------------------------
// Launch. Input order (setup_inputs dict): ufeat, ifeat, W1, b1, W2, b2,
// src_idx, dst_idx. Output: [E,5] fp32.
// ---------------------------------------------------------------------------
extern "C" void kernel_launch(void* const* d_in, const int* in_sizes, int n_in,
                              void* d_out, int out_size) {
    (void)in_sizes; (void)n_in; (void)out_size;
    const float* ufeat = (const float*)d_in[0];
    const float* ifeat = (const float*)d_in[1];
    const float* W1    = (const float*)d_in[2];
    const float* b1    = (const float*)d_in[3];
    const float* W2    = (const float*)d_in[4];
    const float* b2    = (const float*)d_in[5];
    const void*  src   = d_in[6];
    const void*  dst   = d_in[7];
    float* out = (float*)d_out;

    __half *U, *I;
    cudaGetSymbolAddress((void**)&U, g_U);
    cudaGetSymbolAddress((void**)&I, g_I);

    detect_idx_kernel<<<1, 256>>>((const long long*)src, (const long long*)dst);
    precompute_kernel<<<(NU + 31) / 32, 256>>>(ufeat, NU, W1, 0,  b1,      U);
    precompute_kernel<<<(NM + 31) / 32, 256>>>(ifeat, NM, W1, 64, nullptr, I);
    edge_kernel<<<2368, 256>>>(src, dst, U, I, W2, b2, out);   // 16 blocks/SM x 148
}

// round 8
// speedup vs baseline: 1.4924x; 1.4924x over previous
#include <cuda_runtime.h>
#include <cuda_fp16.h>
#include <cstdint>

#define NU 100000
#define NM 50000
#define EDGES 1000000
#define HID 128
#define DIM 64

// Precomputed per-node projections (fp16). __device__ globals = allowed scratch.
__device__ __half g_U[(size_t)NU * HID];
__device__ __half g_I[(size_t)NM * HID];
__device__ int g_idx32;   // 1 if index arrays are int32, 0 if int64

// ---------------------------------------------------------------------------
// Detect index dtype: int32 data read as int64 has nonzero hi words.
// ---------------------------------------------------------------------------
__global__ void detect_idx_kernel(const long long* __restrict__ src,
                                  const long long* __restrict__ dst) {
    long long v = src[threadIdx.x];
    long long w = dst[threadIdx.x];
    int any = (((unsigned long long)v >> 32) != 0ull) |
              (((unsigned long long)w >> 32) != 0ull);
    any = __syncthreads_or(any);
    if (threadIdx.x == 0) g_idx32 = any;
}

// ---------------------------------------------------------------------------
// Precompute: C[r][j] = sum_k A[r][k] * W1[j][kOff + k]  (+ b1[j] if given)
// A: [R,64] fp32, W1: [128,128] row-major, C: [R,128] fp16.
// Block = 256 threads, 32 rows x 128 cols. Thread: 4 rows x 4 cols.
// R5 fix: Wt fill is COALESCED over k (lane-fast k), Wt padded to 132
// floats/row so float4 reads stay 16B-aligned. Was 1.2 GB of uncoalesced
// L2 sector traffic across all blocks; now ~150 MB.
// ---------------------------------------------------------------------------
#define HIDP 132   // HID + 4 pad: keeps 16B alignment, breaks STS conflicts

__global__ __launch_bounds__(256) void precompute_kernel(
    const float* __restrict__ A, int R,
    const float* __restrict__ W1, int kOff,
    const float* __restrict__ b1,     // may be null
    __half* __restrict__ C)
{
    __shared__ float Wt[DIM][HIDP];   // Wt[k][j] = W1[j][kOff+k]  (~33.8 KB)
    __shared__ float As[32][DIM];     // A tile                     (8 KB)

    const int tid = threadIdx.x;
    const int r0  = blockIdx.x * 32;

    // Coalesced: lane-fast index is k (contiguous within a W1 row).
    #pragma unroll
    for (int idx = tid; idx < DIM * HID; idx += 256) {
        int k = idx & 63;         // 0..63, contiguous per lane
        int j = idx >> 6;         // 0..127
        Wt[k][j] = W1[j * 128 + kOff + k];
    }
    for (int idx = tid; idx < 32 * DIM; idx += 256) {
        int r = idx >> 6, c = idx & 63;
        int gr = r0 + r;
        As[r][c] = (gr < R) ? A[(size_t)gr * DIM + c] : 0.f;
    }
    __syncthreads();

    const int tx = tid & 31;   // output column group: cols tx*4 .. tx*4+3
    const int ty = tid >> 5;   // rows ty, ty+8, ty+16, ty+24

    float acc[4][4];
    #pragma unroll
    for (int r = 0; r < 4; r++)
        #pragma unroll
        for (int c = 0; c < 4; c++) acc[r][c] = 0.f;

    #pragma unroll 8
    for (int k = 0; k < DIM; k++) {
        float4 w = *(const float4*)&Wt[k][tx * 4];   // row base 528B: 16B-aligned
        #pragma unroll
        for (int r = 0; r < 4; r++) {
            float a = As[ty + r * 8][k];   // warp-broadcast LDS
            acc[r][0] = fmaf(a, w.x, acc[r][0]);
            acc[r][1] = fmaf(a, w.y, acc[r][1]);
            acc[r][2] = fmaf(a, w.z, acc[r][2]);
            acc[r][3] = fmaf(a, w.w, acc[r][3]);
        }
    }

    float4 bb = make_float4(0.f, 0.f, 0.f, 0.f);
    if (b1) bb = *(const float4*)&b1[tx * 4];

    #pragma unroll
    for (int r = 0; r < 4; r++) {
        int gr = r0 + ty + r * 8;
        if (gr < R) {
            __half2 h0 = __floats2half2_rn(acc[r][0] + bb.x, acc[r][1] + bb.y);
            __half2 h1 = __floats2half2_rn(acc[r][2] + bb.z, acc[r][3] + bb.w);
            __half2* cp = (__half2*)(C + (size_t)gr * HID + tx * 4);
            cp[0] = h0;
            cp[1] = h1;
        }
    }
}

// ---------------------------------------------------------------------------
// Edge pass: out[e][c] = sum_j relu(U[src[e]][j] + I[dst[e]][j]) * W2[c][j] + b2[c]
// 2 edges/warp, 16 lanes/edge, 8 j's/lane.
// R5: add+relu in half2 domain (HADD2+HMAX2), dot via packed fma.rn.f32x2
// (fp32 accumulate, two partials per reg). ~18% fewer warp-instrs/edge.
// ---------------------------------------------------------------------------
__device__ __forceinline__ unsigned long long pack_f32x2(float lo, float hi) {
    unsigned long long p;
    asm("mov.b64 %0, {%1, %2};" : "=l"(p)
        : "r"(__float_as_uint(lo)), "r"(__float_as_uint(hi)));
    return p;
}

__device__ __forceinline__ void edge_body(
    long long e, long long s, long long d, int g,
    const __half* __restrict__ U, const __half* __restrict__ I,
    const unsigned long long* __restrict__ w2q,   // 20 packed f32x2
    float b2sel, float* __restrict__ out)
{
    uint4 uv = *(const uint4*)(U + (size_t)s * HID + g * 8);
    uint4 iv = *(const uint4*)(I + (size_t)d * HID + g * 8);

    const __half2* u2 = (const __half2*)&uv;
    const __half2* i2 = (const __half2*)&iv;
    const __half2 z = __float2half2_rn(0.f);

    unsigned long long h2[4];
    #pragma unroll
    for (int t = 0; t < 4; t++) {
        __half2 hv = __hmax2(__hadd2(u2[t], i2[t]), z);   // relu in half domain
        float2 f = __half22float2(hv);
        h2[t] = pack_f32x2(f.x, f.y);
    }

    float accs[5];
    #pragma unroll
    for (int c = 0; c < 5; c++) {
        unsigned long long a = 0ull;                      // two fp32 partials
        #pragma unroll
        for (int t = 0; t < 4; t++)
            asm("fma.rn.f32x2 %0, %1, %2, %3;"
                : "=l"(a) : "l"(h2[t]), "l"(w2q[c * 4 + t]), "l"(a));
        unsigned int lo, hi;
        asm("mov.b64 {%0, %1}, %2;" : "=r"(lo), "=r"(hi) : "l"(a));
        accs[c] = __uint_as_float(lo) + __uint_as_float(hi);
    }

    // reduce across the 16 lanes of this edge-group
    #pragma unroll
    for (int off = 8; off >= 1; off >>= 1) {
        #pragma unroll
        for (int c = 0; c < 5; c++)
            accs[c] += __shfl_xor_sync(0xffffffffu, accs[c], off);
    }

    if (g < 5) {
        float v = accs[0];
        if (g == 1) v = accs[1];
        else if (g == 2) v = accs[2];
        else if (g == 3) v = accs[3];
        else if (g == 4) v = accs[4];
        out[e * 5 + g] = v + b2sel;
    }
}

__global__ __launch_bounds__(256) void edge_kernel(
    const void* __restrict__ src_raw, const void* __restrict__ dst_raw,
    const __half* __restrict__ U, const __half* __restrict__ I,
    const float* __restrict__ W2, const float* __restrict__ b2,
    float* __restrict__ out)
{
    const int lane = threadIdx.x & 31;
    const int g    = lane & 15;      // j-group within my edge
    const int sub  = lane >> 4;      // which edge of the warp's pair
    const int warpId = (blockIdx.x * blockDim.x + threadIdx.x) >> 5;
    const int nWarps = (gridDim.x * blockDim.x) >> 5;

    // Preload W2 slice as 20 packed f32x2: W2[c][g*8 .. g*8+7]
    unsigned long long w2q[20];
    #pragma unroll
    for (int c = 0; c < 5; c++) {
        float4 a = *(const float4*)(W2 + c * HID + g * 8);
        float4 b = *(const float4*)(W2 + c * HID + g * 8 + 4);
        w2q[c * 4 + 0] = pack_f32x2(a.x, a.y);
        w2q[c * 4 + 1] = pack_f32x2(a.z, a.w);
        w2q[c * 4 + 2] = pack_f32x2(b.x, b.y);
        w2q[c * 4 + 3] = pack_f32x2(b.z, b.w);
    }
    const float b2sel = b2[g < 5 ? g : 0];

    const int nPairs = EDGES / 2;
    if (g_idx32) {
        const int* src32 = (const int*)src_raw;
        const int* dst32 = (const int*)dst_raw;
        for (int p = warpId; p < nPairs; p += nWarps) {
            const long long e = (long long)p * 2 + sub;
            edge_body(e, src32[e], dst32[e], g, U, I, w2q, b2sel, out);
        }
    } else {
        const long long* src64 = (const long long*)src_raw;
        const long long* dst64 = (const long long*)dst_raw;
        for (int p = warpId; p < nPairs; p += nWarps) {
            const long long e = (long long)p * 2 + sub;
            edge_body(e, src64[e], dst64[e], g, U, I, w2q, b2sel, out);
        }
    }
}

// ---------------------------------------------------------------------------
// Launch. Inputs: ufeat, ifeat, W1, b1, W2, b2, src_idx, dst_idx. Out: [E,5] f32.
// ---------------------------------------------------------------------------
extern "C" void kernel_launch(void* const* d_in, const int* in_sizes, int n_in,
                              void* d_out, int out_size) {
    (void)in_sizes; (void)n_in; (void)out_size;
    const float* ufeat = (const float*)d_in[0];
    const float* ifeat = (const float*)d_in[1];
    const float* W1    = (const float*)d_in[2];
    const float* b1    = (const float*)d_in[3];
    const float* W2    = (const float*)d_in[4];
    const float* b2    = (const float*)d_in[5];
    const void*  src   = d_in[6];
    const void*  dst   = d_in[7];
    float* out = (float*)d_out;

    __half *U, *I;
    cudaGetSymbolAddress((void**)&U, g_U);
    cudaGetSymbolAddress((void**)&I, g_I);

    detect_idx_kernel<<<1, 256>>>((const long long*)src, (const long long*)dst);
    precompute_kernel<<<(NU + 31) / 32, 256>>>(ufeat, NU, W1, 0,  b1,      U);
    precompute_kernel<<<(NM + 31) / 32, 256>>>(ifeat, NM, W1, 64, nullptr, I);
    edge_kernel<<<2368, 256>>>(src, dst, U, I, W2, b2, out);
}